// round 11
// baseline (speedup 1.0000x reference)
#include <cuda_runtime.h>
#include <cstdint>

#define NQ   14
#define NL   4
#define DIM  16384
#define NT   1024
#define SEQL 8

typedef unsigned long long ull;

__device__ __forceinline__ ull f2mul(ull a, ull b) {
    ull d; asm("mul.rn.f32x2 %0, %1, %2;" : "=l"(d) : "l"(a), "l"(b)); return d;
}
__device__ __forceinline__ ull f2fma(ull a, ull b, ull c) {
    ull d; asm("fma.rn.f32x2 %0, %1, %2, %3;" : "=l"(d) : "l"(a), "l"(b), "l"(c)); return d;
}
__device__ __forceinline__ ull f2add(ull a, ull b) {
    ull d; asm("add.rn.f32x2 %0, %1, %2;" : "=l"(d) : "l"(a), "l"(b)); return d;
}
__device__ __forceinline__ ull pk(float lo, float hi) {
    ull r; asm("mov.b64 %0, {%1, %2};" : "=l"(r) : "f"(lo), "f"(hi)); return r;
}
__device__ __forceinline__ void upk(ull v, float& lo, float& hi) {
    asm("mov.b64 {%0, %1}, %2;" : "=f"(lo), "=f"(hi) : "l"(v));
}
__device__ __forceinline__ ull lswap(ull v) {
    float lo, hi; upk(v, lo, hi); return pk(hi, lo);
}

// pair-index swizzle: b0=j0^j6, b1=j1^j4, b2=j2^j5, b3=j3^j6 (XOR-linear)
__device__ __forceinline__ int swzd(int j) {
    return j ^ ((j >> 3) & 6) ^ (((j >> 6) & 1) * 9);
}

// 7-coeff SU(2) packed butterfly: u00=X+iY, u01=Z+iW, u10=-conj(u01), u11=conj(u00)
// table ull idx: 0:X 1:Y 2:-Y 3:Z 4:-Z 5:W 6:-W (duplicated pairs)
template<int NB, int J>
__device__ __forceinline__ void gateP7(ull* re, ull* im, const ull* g) {
    ull X = g[0], Y = g[1], nY = g[2], Z = g[3], nZ = g[4], W = g[5], nW = g[6];
#pragma unroll
    for (int k = 0; k < (1 << NB); ++k)
        if (!(k & (1 << J))) {
            const int m = k | (1 << J);
            ull p0r = re[k], p0i = im[k], p1r = re[m], p1i = im[m];
            ull n0r = f2fma(nW, p1i, f2fma(Z, p1r, f2fma(nY, p0i, f2mul(X, p0r))));
            ull n0i = f2fma(W,  p1r, f2fma(Z, p1i, f2fma(Y,  p0r, f2mul(X, p0i))));
            ull n1r = f2fma(Y,  p1i, f2fma(X, p1r, f2fma(nW, p0i, f2mul(nZ, p0r))));
            ull n1i = f2fma(nY, p1r, f2fma(X, p1i, f2fma(W,  p0r, f2mul(nZ, p0i))));
            re[k] = n0r; im[k] = n0i; re[m] = n1r; im[m] = n1i;
        }
}

template<int NB, int JC, int JT>
__device__ __forceinline__ void cnotP(ull* re, ull* im) {
#pragma unroll
    for (int k = 0; k < (1 << NB); ++k)
        if ((k & (1 << JC)) && !(k & (1 << JT))) {
            const int m = k | (1 << JT);
            ull t = re[k]; re[k] = re[m]; re[m] = t;
            t = im[k]; im[k] = im[m]; im[m] = t;
        }
}
template<int NB, int JT>
__device__ __forceinline__ void cswapHalf(ull* re, ull* im, bool pred) {
    if (pred) {
#pragma unroll
        for (int k = 0; k < (1 << NB); ++k)
            if (!(k & (1 << JT))) {
                const int m = k | (1 << JT);
                ull t = re[k]; re[k] = re[m]; re[m] = t;
                t = im[k]; im[k] = im[m]; im[m] = t;
            }
    }
}

template<int J0,int J1,int J2>
__device__ __forceinline__ void load8(ull* re, ull* im,
                                      const ull* reP, const ull* imP, int pjb) {
#pragma unroll
    for (int k = 0; k < 8; ++k) {
        int joff = ((k&1)?(1<<J0):0) | ((k&2)?(1<<J1):0) | ((k&4)?(1<<J2):0);
        int a = pjb ^ swzd(joff);
        re[k] = reP[a]; im[k] = imP[a];
    }
}
template<int J0,int J1,int J2>
__device__ __forceinline__ void store8(const ull* re, const ull* im,
                                       ull* reP, ull* imP, int pjb) {
#pragma unroll
    for (int k = 0; k < 8; ++k) {
        int joff = ((k&1)?(1<<J0):0) | ((k&2)?(1<<J1):0) | ((k&4)?(1<<J2):0);
        int a = pjb ^ swzd(joff);
        reP[a] = re[k]; imP[a] = im[k];
    }
}

__device__ __forceinline__ float2 cmulf(float2 a, float2 b) {
    return make_float2(a.x*b.x - a.y*b.y, a.x*b.y + a.y*b.x);
}

// wire-13 (amp0 lane) butterfly; table ull idx: 0:C1 1:C2 2:nC2 3:C3 4:C4 5:nC4
__device__ __forceinline__ void gateLane8(ull* re, ull* im, const ull* g) {
    ull C1 = g[0], C2 = g[1], nC2 = g[2], C3 = g[3], C4 = g[4], nC4 = g[5];
#pragma unroll
    for (int k = 0; k < 8; ++k) {
        ull qr = lswap(re[k]), qi = lswap(im[k]);
        ull nr = f2fma(C4,  qi, f2fma(C3, qr, f2fma(C2,  im[k], f2mul(C1, re[k]))));
        ull ni = f2fma(nC4, qr, f2fma(C3, qi, f2fma(nC2, re[k], f2mul(C1, im[k]))));
        re[k] = nr; im[k] = ni;
    }
}

// carried CNOT(13,0): ctrl amp0 (hi lane), tgt amp13 (cube bit 2)
__device__ __forceinline__ void carriedSwap3(ull* re, ull* im) {
#pragma unroll
    for (int k = 0; k < 4; ++k) {
        float alo, ahi, blo, bhi;
        upk(re[k], alo, ahi); upk(re[k|4], blo, bhi);
        re[k] = pk(alo, bhi); re[k|4] = pk(blo, ahi);
        upk(im[k], alo, ahi); upk(im[k|4], blo, bhi);
        im[k] = pk(alo, bhi); im[k|4] = pk(blo, ahi);
    }
}

__global__ void __launch_bounds__(NT, 1)
vqc_kernel(const float* __restrict__ x,    const float* __restrict__ w_in,
           const float* __restrict__ b_in, const float* __restrict__ wts,
           const float* __restrict__ w_out,const float* __restrict__ b_out,
           float* __restrict__ out)
{
    extern __shared__ float smem[];
    float* reF  = smem;
    float* imF  = smem + DIM;
    float* gmat = smem + 2 * DIM;     // 3*14*16 = 672
    float* enc  = gmat + 672;         // 28
    float* red  = enc + 28;           // 464
    ull* reP = (ull*)reF;
    ull* imP = (ull*)imF;
    float2* ftab = (float2*)red;      // init factor table (56 floats, reused)

    const int b = blockIdx.x, tid = threadIdx.x;

    if (tid < NQ) {
        float acc = b_in[tid];
#pragma unroll
        for (int s2 = 0; s2 < SEQL; ++s2) acc += x[b*SEQL + s2] * w_in[tid*SEQL + s2];
        enc[2*tid]     = cospif(0.5f * acc);
        enc[2*tid + 1] = sinpif(0.5f * acc);
    }
    __syncthreads();

    if (tid < NQ * NL) {
        int i = tid % NQ, j = tid / NQ;
        const float* w = wts + (i*NL + j)*3;
        float cx = cosf(0.5f*w[0]), sx = sinf(0.5f*w[0]);
        float cy = cosf(0.5f*w[1]), sy = sinf(0.5f*w[1]);
        float cz = cosf(0.5f*w[2]), sz = sinf(0.5f*w[2]);
        if (j == 3) { cz = 1.f; sz = 0.f; }            // final RZ phase-only
        float2 m00 = make_float2( cy*cx,  sy*sx);
        float2 m01 = make_float2(-sy*cx, -cy*sx);
        float2 e0 = make_float2(cz, -sz);
        float2 u00 = cmulf(e0, m00), u01 = cmulf(e0, m01);
        float X = u00.x, Y = u00.y, Z = u01.x, W = u01.y;
        if (j == 0) {
            float c = enc[2*i], s = enc[2*i+1];
            int t = 13 - i;
            ftab[t*2 + 0] = make_float2(X*c + Z*s,  Y*c + W*s);
            ftab[t*2 + 1] = make_float2(-Z*c + X*s, W*c - Y*s);   // u10,u11 row
        } else {
            float* g = gmat + ((j-1)*NQ + i)*16;
            if (i < 13) {
                g[0]=X;  g[1]=X;  g[2]=Y;  g[3]=Y;  g[4]=-Y; g[5]=-Y;
                g[6]=Z;  g[7]=Z;  g[8]=-Z; g[9]=-Z; g[10]=W; g[11]=W;
                g[12]=-W; g[13]=-W; g[14]=0.f; g[15]=0.f;
            } else {   // wire 13 lane-distinct: C1,C2,nC2,C3,C4,nC4
                g[0]=X;  g[1]=X;   g[2]=-Y; g[3]=Y;   g[4]=Y;  g[5]=-Y;
                g[6]=Z;  g[7]=-Z;  g[8]=-W; g[9]=-W;  g[10]=W; g[11]=W;
                g[12]=0.f; g[13]=0.f; g[14]=0.f; g[15]=0.f;
            }
        }
    }
    __syncthreads();

    // init: state AFTER layer 1 (ring folded: q = (p^(p>>1)) ^ ((p&1)*0x3000))
    {
        int ql = (tid ^ (tid >> 1)) & 0x1FF;           // q0..q8 from tid
        float2 lowp = make_float2(1.f, 0.f);
#pragma unroll
        for (int t = 0; t < 9; ++t)
            lowp = cmulf(lowp, ftab[t*2 + ((ql >> t) & 1)]);
        float2 F0[5], F1[5];
#pragma unroll
        for (int t = 0; t < 5; ++t) { F0[t] = ftab[(9+t)*2]; F1[t] = ftab[(9+t)*2+1]; }
        int t0 = tid & 1, t9 = (tid >> 9) & 1;
#pragma unroll 4
        for (int k = 0; k < DIM/NT; ++k) {             // k = amp bits 10..13
            int q9  = t9 ^ (k & 1);
            int q10 = (k ^ (k >> 1)) & 1;
            int q11 = ((k >> 1) ^ (k >> 2)) & 1;
            int q12 = (((k >> 2) ^ (k >> 3)) & 1) ^ t0;
            int q13 = ((k >> 3) & 1) ^ t0;
            float2 p = lowp;
            p = cmulf(p, q9  ? F1[0] : F0[0]);
            p = cmulf(p, q10 ? F1[1] : F0[1]);
            p = cmulf(p, q11 ? F1[2] : F0[2]);
            p = cmulf(p, q12 ? F1[3] : F0[3]);
            p = cmulf(p, q13 ? F1[4] : F0[4]);
            int idx = tid + (k << 10);
            int a = 2*swzd(idx >> 1) + (idx & 1);
            reF[a] = p.x; imF[a] = p.y;
        }
    }
    __syncthreads();

    // layers 2..4. wire w <-> amp bit (13-w); j bit b <-> amp bit b+1.
#pragma unroll 1
    for (int jl = 0; jl < 3; ++jl) {
        const float* gl = gmat + jl * NQ * 16;
        {   // P1 cube j{10,11,12}=amp{11,12,13}: carry, w0,w1,w2,w13, CNOT(0,1)(1,2)
            int pjb = swzd(tid);
            ull re[8], im[8];
            load8<10,11,12>(re, im, reP, imP, pjb);
            if (jl > 0) carriedSwap3(re, im);
            gateP7<3,2>(re, im, (const ull*)(gl + 0*16));
            gateP7<3,1>(re, im, (const ull*)(gl + 1*16));
            gateP7<3,0>(re, im, (const ull*)(gl + 2*16));
            gateLane8(re, im, (const ull*)(gl + 13*16));
            cnotP<3,2,1>(re, im); cnotP<3,1,0>(re, im);
            store8<10,11,12>(re, im, reP, imP, pjb);
        }
        __syncthreads();
        {   // P2 cube j{7,8,9}=amp{8,9,10}: w3,w4,w5; CNOT(2,3)pred,(3,4)(4,5)
            int pjb = swzd((tid & 127) | ((tid >> 7) << 10));
            ull re[8], im[8];
            load8<7,8,9>(re, im, reP, imP, pjb);
            gateP7<3,2>(re, im, (const ull*)(gl + 3*16));
            gateP7<3,1>(re, im, (const ull*)(gl + 4*16));
            gateP7<3,0>(re, im, (const ull*)(gl + 5*16));
            cswapHalf<3,2>(re, im, (tid >> 7) & 1);     // ctrl amp11=j10=tid7
            cnotP<3,2,1>(re, im); cnotP<3,1,0>(re, im);
            store8<7,8,9>(re, im, reP, imP, pjb);
        }
        __syncthreads();
        {   // P3 cube j{4,5,6}=amp{5,6,7}: w6,w7,w8; CNOT(5,6)pred,(6,7)(7,8)
            int pjb = swzd((tid & 15) | ((tid >> 4) << 7));
            ull re[8], im[8];
            load8<4,5,6>(re, im, reP, imP, pjb);
            gateP7<3,2>(re, im, (const ull*)(gl + 6*16));
            gateP7<3,1>(re, im, (const ull*)(gl + 7*16));
            gateP7<3,0>(re, im, (const ull*)(gl + 8*16));
            cswapHalf<3,2>(re, im, (tid >> 4) & 1);     // ctrl amp8=j7=tid4
            cnotP<3,2,1>(re, im); cnotP<3,1,0>(re, im);
            store8<4,5,6>(re, im, reP, imP, pjb);
        }
        __syncthreads();
        {   // P4 cube j{1,2,3}=amp{2,3,4}: w9,w10,w11; CNOT(8,9)pred,(9,10)(10,11)
            int pjb = swzd((tid & 1) | ((tid >> 1) << 4));
            ull re[8], im[8];
            load8<1,2,3>(re, im, reP, imP, pjb);
            gateP7<3,2>(re, im, (const ull*)(gl + 9*16));
            gateP7<3,1>(re, im, (const ull*)(gl + 10*16));
            gateP7<3,0>(re, im, (const ull*)(gl + 11*16));
            cswapHalf<3,2>(re, im, (tid >> 1) & 1);     // ctrl amp5=j4=tid1
            cnotP<3,2,1>(re, im); cnotP<3,1,0>(re, im);
            store8<1,2,3>(re, im, reP, imP, pjb);
        }
        __syncthreads();
        if (jl < 2) {
            // P5 cube j{0,1,2}=amp{1,2,3}: w12; CNOT(11,12),(12,13); (13,0) carried
            int pjb = swzd(tid << 3);
            ull re[8], im[8];
            load8<0,1,2>(re, im, reP, imP, pjb);
            gateP7<3,0>(re, im, (const ull*)(gl + 12*16));
            cnotP<3,1,0>(re, im);                       // ctrl amp2=bit1, tgt amp1
#pragma unroll
            for (int k = 1; k < 8; k += 2) { re[k] = lswap(re[k]); im[k] = lswap(im[k]); }
            store8<0,1,2>(re, im, reP, imP, pjb);
            __syncthreads();
        }
    }

    // fused final P5 + readout; CNOT(11,12),(12,13),(13,0) folded as relabels.
    // bits: lane=amp0, k0..k2=amp1..3, tid0..tid9=amp4..13
    {
        const float* gl = gmat + 2 * NQ * 16;
        int pjb = swzd(tid << 3);
        ull re[8], im[8];
        load8<0,1,2>(re, im, reP, imP, pjb);
        gateP7<3,0>(re, im, (const ull*)(gl + 12*16));  // w12

        ull accP = 0, acc10 = 0, acc11 = 0, acc12 = 0;
        const ull NEG1 = 0xBF800000BF800000ull;
#pragma unroll
        for (int k = 0; k < 8; ++k) {
            ull p = f2fma(im[k], im[k], f2mul(re[k], re[k]));
            accP = f2add(accP, p);
            acc10 = ((k >> 2) & 1)      ? f2fma(p, NEG1, acc10) : f2add(acc10, p);
            acc11 = ((k >> 1) & 1)      ? f2fma(p, NEG1, acc11) : f2add(acc11, p);
            acc12 = ((k ^ (k >> 1)) & 1)? f2fma(p, NEG1, acc12) : f2add(acc12, p);
        }
        float z[NQ];
        float Pl, Ph;   upk(accP, Pl, Ph);   float Ps = Pl + Ph;
        float l10, h10; upk(acc10, l10, h10);
        float l11, h11; upk(acc11, l11, h11);
        float l12, h12; upk(acc12, l12, h12);
        z[1] = (tid & 256) ? -Ps : Ps;   // amp12 = tid8
        z[2] = (tid & 128) ? -Ps : Ps;
        z[3] = (tid & 64)  ? -Ps : Ps;
        z[4] = (tid & 32)  ? -Ps : Ps;
        z[5] = (tid & 16)  ? -Ps : Ps;
        z[6] = (tid & 8)   ? -Ps : Ps;
        z[7] = (tid & 4)   ? -Ps : Ps;
        z[8] = (tid & 2)   ? -Ps : Ps;
        z[9] = (tid & 1)   ? -Ps : Ps;   // amp4 = tid0
        z[10] = l10 + h10;               // amp3 = k2
        z[11] = l11 + h11;               // amp2 = k1
        z[12] = l12 + h12;               // k0^k1
        z[13] = l12 - h12;               // lane ^ k0^k1
        z[0]  = (tid & 512) ? -z[13] : z[13];   // tid9 ^ (lane^k0^k1)

#pragma unroll
        for (int w = 0; w < NQ; ++w)
#pragma unroll
            for (int o = 16; o; o >>= 1)
                z[w] += __shfl_xor_sync(0xffffffffu, z[w], o);

        __syncthreads();
        if ((tid & 31) == 0) {
            int wr = tid >> 5;
#pragma unroll
            for (int w = 0; w < NQ; ++w) red[wr*NQ + w] = z[w];
        }
        __syncthreads();
        if (tid < NQ) {
            float s = 0.f;
#pragma unroll
            for (int wr = 0; wr < NT/32; ++wr) s += red[wr*NQ + tid];
            red[448 + tid] = s * w_out[tid];
        }
        __syncthreads();
        if (tid == 0) {
            float o = b_out[0];
#pragma unroll
            for (int w = 0; w < NQ; ++w) o += red[448 + w];
            out[b] = o;
        }
    }
}

extern "C" void kernel_launch(void* const* d_in, const int* in_sizes, int n_in,
                              void* d_out, int out_size)
{
    const float* x     = (const float*)d_in[0];
    const float* w_in  = (const float*)d_in[1];
    const float* b_in  = (const float*)d_in[2];
    const float* wts   = (const float*)d_in[3];
    const float* w_out = (const float*)d_in[4];
    const float* b_out = (const float*)d_in[5];
    float* out = (float*)d_out;

    const int B = in_sizes[0] / SEQL;                      // 1024
    const int smem = (2*DIM + 672 + 28 + 464) * (int)sizeof(float);

    cudaFuncSetAttribute(vqc_kernel, cudaFuncAttributeMaxDynamicSharedMemorySize, smem);
    vqc_kernel<<<B, NT, smem>>>(x, w_in, b_in, wts, w_out, b_out, out);
}

// round 12
// speedup vs baseline: 1.2271x; 1.2271x over previous
#include <cuda_runtime.h>
#include <cstdint>

#define NQ   14
#define NL   4
#define DIM  16384
#define NT   512
#define SEQL 8

typedef unsigned long long ull;

__device__ __forceinline__ ull f2mul(ull a, ull b) {
    ull d; asm("mul.rn.f32x2 %0, %1, %2;" : "=l"(d) : "l"(a), "l"(b)); return d;
}
__device__ __forceinline__ ull f2fma(ull a, ull b, ull c) {
    ull d; asm("fma.rn.f32x2 %0, %1, %2, %3;" : "=l"(d) : "l"(a), "l"(b), "l"(c)); return d;
}
__device__ __forceinline__ ull f2add(ull a, ull b) {
    ull d; asm("add.rn.f32x2 %0, %1, %2;" : "=l"(d) : "l"(a), "l"(b)); return d;
}
__device__ __forceinline__ ull pk(float lo, float hi) {
    ull r; asm("mov.b64 %0, {%1, %2};" : "=l"(r) : "f"(lo), "f"(hi)); return r;
}
__device__ __forceinline__ void upk(ull v, float& lo, float& hi) {
    asm("mov.b64 {%0, %1}, %2;" : "=f"(lo), "=f"(hi) : "l"(v));
}
__device__ __forceinline__ ull lswap(ull v) {
    float lo, hi; upk(v, lo, hi); return pk(hi, lo);
}

__device__ __forceinline__ int swz4(int j) { return j ^ ((j >> 4) & 15); }

template<int NB, int J>
__device__ __forceinline__ void gateP(ull* re, ull* im, const ull* g) {
    ull Ax = g[0], Ay = g[1], nAy = g[2], Az = g[3], Aw = g[4], nAw = g[5];
    ull Bx = g[6], By = g[7], nBy = g[8], Bz = g[9], Bw = g[10], nBw = g[11];
#pragma unroll
    for (int k = 0; k < (1 << NB); ++k)
        if (!(k & (1 << J))) {
            const int m = k | (1 << J);
            ull p0r = re[k], p0i = im[k], p1r = re[m], p1i = im[m];
            ull n0r = f2fma(nAw, p1i, f2fma(Az, p1r, f2fma(nAy, p0i, f2mul(Ax, p0r))));
            ull n0i = f2fma(Aw,  p1r, f2fma(Az, p1i, f2fma(Ay,  p0r, f2mul(Ax, p0i))));
            ull n1r = f2fma(nBw, p1i, f2fma(Bz, p1r, f2fma(nBy, p0i, f2mul(Bx, p0r))));
            ull n1i = f2fma(Bw,  p1r, f2fma(Bz, p1i, f2fma(By,  p0r, f2mul(Bx, p0i))));
            re[k] = n0r; im[k] = n0i; re[m] = n1r; im[m] = n1i;
        }
}

template<int NB, int JC, int JT>
__device__ __forceinline__ void cnotP(ull* re, ull* im) {
#pragma unroll
    for (int k = 0; k < (1 << NB); ++k)
        if ((k & (1 << JC)) && !(k & (1 << JT))) {
            const int m = k | (1 << JT);
            ull t = re[k]; re[k] = re[m]; re[m] = t;
            t = im[k]; im[k] = im[m]; im[m] = t;
        }
}

template<int NB, int JT>
__device__ __forceinline__ void cswapHalf(ull* re, ull* im, bool pred) {
    if (pred) {
#pragma unroll
        for (int k = 0; k < (1 << NB); ++k)
            if (!(k & (1 << JT))) {
                const int m = k | (1 << JT);
                ull t = re[k]; re[k] = re[m]; re[m] = t;
                t = im[k]; im[k] = im[m]; im[m] = t;
            }
    }
}

template<int J0,int J1,int J2,int J3>
__device__ __forceinline__ void load16(ull* re, ull* im,
                                       const ull* reP, const ull* imP, int pjb) {
#pragma unroll
    for (int k = 0; k < 16; ++k) {
        int joff = ((k&1)?(1<<J0):0) | ((k&2)?(1<<J1):0)
                 | ((k&4)?(1<<J2):0) | ((k&8)?(1<<J3):0);
        int a = pjb ^ (joff ^ ((joff >> 4) & 15));
        re[k] = reP[a]; im[k] = imP[a];
    }
}
template<int J0,int J1,int J2,int J3>
__device__ __forceinline__ void store16(const ull* re, const ull* im,
                                        ull* reP, ull* imP, int pjb) {
#pragma unroll
    for (int k = 0; k < 16; ++k) {
        int joff = ((k&1)?(1<<J0):0) | ((k&2)?(1<<J1):0)
                 | ((k&4)?(1<<J2):0) | ((k&8)?(1<<J3):0);
        int a = pjb ^ (joff ^ ((joff >> 4) & 15));
        reP[a] = re[k]; imP[a] = im[k];
    }
}

__device__ __forceinline__ float2 cmulf(float2 a, float2 b) {
    return make_float2(a.x*b.x - a.y*b.y, a.x*b.y + a.y*b.x);
}

__device__ __forceinline__ void gateLaneAll(ull* re, ull* im, const ull* g13) {
    ull C1 = g13[0], C2 = g13[1], nC2 = g13[2],
        C3 = g13[3], C4 = g13[4], nC4 = g13[5];
#pragma unroll
    for (int k = 0; k < 16; ++k) {
        ull qr = lswap(re[k]), qi = lswap(im[k]);
        ull nr = f2fma(C4,  qi, f2fma(C3, qr, f2fma(C2,  im[k], f2mul(C1, re[k]))));
        ull ni = f2fma(nC4, qr, f2fma(C3, qi, f2fma(nC2, re[k], f2mul(C1, im[k]))));
        re[k] = nr; im[k] = ni;
    }
}

__device__ __forceinline__ void carriedSwap(ull* re, ull* im) {
#pragma unroll
    for (int k1 = 0; k1 < 8; ++k1) {
        float alo, ahi, blo, bhi;
        upk(re[k1], alo, ahi); upk(re[k1|8], blo, bhi);
        re[k1] = pk(alo, bhi); re[k1|8] = pk(blo, ahi);
        upk(im[k1], alo, ahi); upk(im[k1|8], blo, bhi);
        im[k1] = pk(alo, bhi); im[k1|8] = pk(blo, ahi);
    }
}

__device__ __forceinline__ void gateShfl(ull* re, ull* im, const ull* gr) {
    ull Ax = gr[0], Ay = gr[1], nAy = gr[2], Az = gr[3], Aw = gr[4], nAw = gr[5];
#pragma unroll
    for (int k = 0; k < 16; ++k) {
        ull qr = __shfl_xor_sync(0xffffffffu, re[k], 1);
        ull qi = __shfl_xor_sync(0xffffffffu, im[k], 1);
        ull nr = f2fma(nAw, qi, f2fma(Az, qr, f2fma(nAy, im[k], f2mul(Ax, re[k]))));
        ull ni = f2fma(Aw,  qr, f2fma(Az, qi, f2fma(Ay,  re[k], f2mul(Ax, im[k]))));
        re[k] = nr; im[k] = ni;
    }
}

__device__ __forceinline__ void pass_a(ull* reP, ull* imP, const float* gl,
                                       int tid, bool carry) {
    int pjb = swz4(tid);
    ull re[16], im[16];
    load16<9,10,11,12>(re, im, reP, imP, pjb);
    if (carry) carriedSwap(re, im);
    gateP<4,3>(re, im, (const ull*)(gl + 0*24));
    gateP<4,2>(re, im, (const ull*)(gl + 1*24));
    gateP<4,1>(re, im, (const ull*)(gl + 2*24));
    gateP<4,0>(re, im, (const ull*)(gl + 3*24));
    gateLaneAll(re, im, (const ull*)(gl + 13*24));
    cnotP<4,3,2>(re, im); cnotP<4,2,1>(re, im); cnotP<4,1,0>(re, im);
    store16<9,10,11,12>(re, im, reP, imP, pjb);
}
__device__ __forceinline__ void pass_b(ull* reP, ull* imP, const float* gl, int tid) {
    int base = (tid & 31) | ((tid >> 5) << 9);
    int pjb = swz4(base);
    ull re[16], im[16];
    load16<5,6,7,8>(re, im, reP, imP, pjb);
    gateP<4,3>(re, im, (const ull*)(gl + 4*24));
    gateP<4,2>(re, im, (const ull*)(gl + 5*24));
    gateP<4,1>(re, im, (const ull*)(gl + 6*24));
    gateP<4,0>(re, im, (const ull*)(gl + 7*24));
    cswapHalf<4,3>(re, im, (tid >> 5) & 1);
    cnotP<4,3,2>(re, im); cnotP<4,2,1>(re, im); cnotP<4,1,0>(re, im);
    store16<5,6,7,8>(re, im, reP, imP, pjb);
}
__device__ __forceinline__ void pass_c(ull* reP, ull* imP, const float* gl,
                                       const float* g8, int tid) {
    int pjb = swz4(tid << 4);
    ull re[16], im[16];
    load16<0,1,2,3>(re, im, reP, imP, pjb);
    gateShfl(re, im, (const ull*)(g8 + (tid & 3) * 12));
    gateP<4,3>(re, im, (const ull*)(gl + 9*24));
    gateP<4,2>(re, im, (const ull*)(gl + 10*24));
    gateP<4,1>(re, im, (const ull*)(gl + 11*24));
    gateP<4,0>(re, im, (const ull*)(gl + 12*24));
    cswapHalf<4,3>(re, im, tid & 1);
    cnotP<4,3,2>(re, im); cnotP<4,2,1>(re, im); cnotP<4,1,0>(re, im);
#pragma unroll
    for (int k = 1; k < 16; k += 2) { re[k] = lswap(re[k]); im[k] = lswap(im[k]); }
    store16<0,1,2,3>(re, im, reP, imP, pjb);
}

__global__ void __launch_bounds__(NT, 1)
vqc_kernel(const float* __restrict__ x,    const float* __restrict__ w_in,
           const float* __restrict__ b_in, const float* __restrict__ wts,
           const float* __restrict__ w_out,const float* __restrict__ b_out,
           float* __restrict__ out)
{
    extern __shared__ float smem[];
    float* reF   = smem;
    float* imF   = smem + DIM;
    float* gmat  = smem + 2 * DIM;          // 1008
    float* g8tab = gmat + 42 * 24;          // 144
    float* enc   = g8tab + 144;             // 28
    float* red   = enc + 28;                // 240
    ull* reP = (ull*)reF;
    ull* imP = (ull*)imF;
    float2* ftab = (float2*)red;            // init factor table (56 floats)

    const int b = blockIdx.x, tid = threadIdx.x;

    if (tid < NQ) {
        float acc = b_in[tid];
#pragma unroll
        for (int s2 = 0; s2 < SEQL; ++s2) acc += x[b*SEQL + s2] * w_in[tid*SEQL + s2];
        enc[2*tid]     = cospif(0.5f * acc);
        enc[2*tid + 1] = sinpif(0.5f * acc);
    }
    __syncthreads();

    if (tid < NQ * NL) {
        int i = tid % NQ, j = tid / NQ;
        const float* w = wts + (i*NL + j)*3;
        float cx = cosf(0.5f*w[0]), sx = sinf(0.5f*w[0]);
        float cy = cosf(0.5f*w[1]), sy = sinf(0.5f*w[1]);
        float cz = cosf(0.5f*w[2]), sz = sinf(0.5f*w[2]);
        if (j == 3) { cz = 1.f; sz = 0.f; }
        float2 m00 = make_float2( cy*cx,  sy*sx);
        float2 m01 = make_float2(-sy*cx, -cy*sx);
        float2 m10 = make_float2( sy*cx, -cy*sx);
        float2 m11 = make_float2( cy*cx, -sy*sx);
        float2 e0 = make_float2(cz, -sz), e1 = make_float2(cz, sz);
        float2 u00 = cmulf(e0, m00), u01 = cmulf(e0, m01);
        float2 u10 = cmulf(e1, m10), u11 = cmulf(e1, m11);
        if (j == 0) {
            float c = enc[2*i], s = enc[2*i+1];
            int t = 13 - i;
            ftab[t*2 + 0] = make_float2(u00.x*c + u01.x*s, u00.y*c + u01.y*s);
            ftab[t*2 + 1] = make_float2(u10.x*c + u11.x*s, u10.y*c + u11.y*s);
        } else if (i == 8) {
            float2 Ca[4] = { u00, u11, u10, u01 };
            float2 Cb[4] = { u01, u10, u11, u00 };
#pragma unroll
            for (int s4 = 0; s4 < 4; ++s4) {
                float* r = g8tab + ((j-1)*4 + s4)*12;
                r[0]=Ca[s4].x; r[1]=Ca[s4].x;  r[2]=Ca[s4].y; r[3]=Ca[s4].y;
                r[4]=-Ca[s4].y; r[5]=-Ca[s4].y; r[6]=Cb[s4].x; r[7]=Cb[s4].x;
                r[8]=Cb[s4].y; r[9]=Cb[s4].y;  r[10]=-Cb[s4].y; r[11]=-Cb[s4].y;
            }
        } else {
            float* g = gmat + ((j-1)*NQ + i)*24;
            if (i < 13) {
                float c[12] = { u00.x, u00.y, -u00.y, u01.x, u01.y, -u01.y,
                                u10.x, u10.y, -u10.y, u11.x, u11.y, -u11.y };
#pragma unroll
                for (int q = 0; q < 12; ++q) { g[2*q] = c[q]; g[2*q+1] = c[q]; }
            } else {
                g[0] = u00.x;  g[1] = u11.x;
                g[2] = -u00.y; g[3] = -u11.y;
                g[4] = u00.y;  g[5] = u11.y;
                g[6] = u01.x;  g[7] = u10.x;
                g[8] = -u01.y; g[9] = -u10.y;
                g[10] = u01.y; g[11] = u10.y;
            }
        }
    }
    __syncthreads();

    // --- layer 2 pass A fused with init: synthesize amps in registers.
    // Entry k holds pair p = tid + (k<<9); idx bits: b0=lane, b1..9=tid0..8,
    // b10..13=k0..3. q = gray(idx) ^ lane*0x3000.
    {
        const float* gl = gmat;
        int gx = tid ^ (tid >> 1);
        float2 P8 = ftab[2 + (gx & 1)];                 // t=1
#pragma unroll
        for (int t = 2; t <= 8; ++t)
            P8 = cmulf(P8, ftab[t*2 + ((gx >> (t-1)) & 1)]);
        float2 Bl0 = cmulf(P8, ftab[0 + (tid & 1)]);
        float2 Bl1 = cmulf(P8, ftab[0 + ((tid & 1) ^ 1)]);
        float2 G00 = cmulf(ftab[24], ftab[26]);
        float2 G01 = cmulf(ftab[24], ftab[27]);
        float2 G10 = cmulf(ftab[25], ftab[26]);
        float2 G11 = cmulf(ftab[25], ftab[27]);
        int t8 = (tid >> 8) & 1;
        ull re[16], im[16];
#pragma unroll
        for (int k = 0; k < 16; ++k) {
            const int k0 = k & 1, k1 = (k >> 1) & 1, k2 = (k >> 2) & 1, k3 = (k >> 3) & 1;
            float2 H3 = cmulf(cmulf(ftab[18 + (t8 ^ k0)], ftab[20 + (k0 ^ k1)]),
                              ftab[22 + (k1 ^ k2)]);
            const int a0 = k2 ^ k3, b0c = k3;           // lane0 selectors (const)
            float2 HL0 = cmulf(H3, a0 ? (b0c ? G11 : G10) : (b0c ? G01 : G00));
            float2 HL1 = cmulf(H3, (a0^1) ? ((b0c^1) ? G11 : G10) : ((b0c^1) ? G01 : G00));
            float2 lo = cmulf(Bl0, HL0);
            float2 hi = cmulf(Bl1, HL1);
            re[k] = pk(lo.x, hi.x);
            im[k] = pk(lo.y, hi.y);
        }
        gateP<4,3>(re, im, (const ull*)(gl + 0*24));
        gateP<4,2>(re, im, (const ull*)(gl + 1*24));
        gateP<4,1>(re, im, (const ull*)(gl + 2*24));
        gateP<4,0>(re, im, (const ull*)(gl + 3*24));
        gateLaneAll(re, im, (const ull*)(gl + 13*24));
        cnotP<4,3,2>(re, im); cnotP<4,2,1>(re, im); cnotP<4,1,0>(re, im);
        store16<9,10,11,12>(re, im, reP, imP, swz4(tid));
    }
    __syncthreads();
    pass_b(reP, imP, gmat, tid);              __syncthreads();
    pass_c(reP, imP, gmat, g8tab, tid);       __syncthreads();

    // --- layer 3 ---
    pass_a(reP, imP, gmat + NQ*24, tid, true);      __syncthreads();
    pass_b(reP, imP, gmat + NQ*24, tid);            __syncthreads();
    pass_c(reP, imP, gmat + NQ*24, g8tab + 48, tid);__syncthreads();

    // --- layer 4: A(carry), B, then C fused with readout ---
    {
        const float* gl = gmat + 2 * NQ * 24;
        const float* g8 = g8tab + 2 * 48;
        pass_a(reP, imP, gl, tid, true);  __syncthreads();
        pass_b(reP, imP, gl, tid);        __syncthreads();

        int pjb = swz4(tid << 4);
        ull re[16], im[16];
        load16<0,1,2,3>(re, im, reP, imP, pjb);
        gateShfl(re, im, (const ull*)(g8 + (tid & 1) * 12));
        gateP<4,3>(re, im, (const ull*)(gl + 9*24));
        gateP<4,2>(re, im, (const ull*)(gl + 10*24));
        gateP<4,1>(re, im, (const ull*)(gl + 11*24));
        gateP<4,0>(re, im, (const ull*)(gl + 12*24));

        ull accP = 0, acc9 = 0, acc10 = 0, acc11 = 0, acc12 = 0;
        const ull NEG1 = 0xBF800000BF800000ull;
#pragma unroll
        for (int k = 0; k < 16; ++k) {
            ull p = f2fma(im[k], im[k], f2mul(re[k], re[k]));
            accP = f2add(accP, p);
            int k3 = (k >> 3) & 1;
            int k23 = ((k >> 2) ^ (k >> 3)) & 1;
            int k123 = ((k >> 1) ^ (k >> 2) ^ (k >> 3)) & 1;
            int kpar = __popc(k) & 1;
            acc9  = k3   ? f2fma(p, NEG1, acc9)  : f2add(acc9,  p);
            acc10 = k23  ? f2fma(p, NEG1, acc10) : f2add(acc10, p);
            acc11 = k123 ? f2fma(p, NEG1, acc11) : f2add(acc11, p);
            acc12 = kpar ? f2fma(p, NEG1, acc12) : f2add(acc12, p);
        }
        float z[NQ];
        {
            float Pl, Ph;  upk(accP, Pl, Ph);   float Ps = Pl + Ph;
            float l9, h9;  upk(acc9, l9, h9);
            float l10,h10; upk(acc10,l10,h10);
            float l11,h11; upk(acc11,l11,h11);
            float l12,h12; upk(acc12,l12,h12);
            int t01 = (tid ^ (tid >> 1)) & 1;
            float f5 = t01 ? -1.f : 1.f;
            z[1] = (tid & 128) ? -Ps : Ps;
            z[2] = (tid & 64)  ? -Ps : Ps;
            z[3] = (tid & 32)  ? -Ps : Ps;
            z[4] = (tid & 16)  ? -Ps : Ps;
            z[5] = (tid & 8)   ? -Ps : Ps;
            z[6] = (tid & 4)   ? -Ps : Ps;
            z[7] = (tid & 2)   ? -Ps : Ps;
            z[8] = t01 ? -Ps : Ps;
            z[9]  = f5 * (l9  + h9);
            z[10] = f5 * (l10 + h10);
            z[11] = f5 * (l11 + h11);
            z[12] = f5 * (l12 + h12);
            z[13] = f5 * (l12 - h12);
            z[0]  = (tid & 256) ? -z[13] : z[13];
        }

#pragma unroll
        for (int w = 0; w < NQ; ++w)
#pragma unroll
            for (int o = 16; o; o >>= 1)
                z[w] += __shfl_xor_sync(0xffffffffu, z[w], o);

        __syncthreads();
        if ((tid & 31) == 0) {
            int wr = tid >> 5;
#pragma unroll
            for (int w = 0; w < NQ; ++w) red[wr*NQ + w] = z[w];
        }
        __syncthreads();
        if (tid < NQ) {
            float s = 0.f;
#pragma unroll
            for (int wr = 0; wr < NT/32; ++wr) s += red[wr*NQ + tid];
            red[224 + tid] = s * w_out[tid];
        }
        __syncthreads();
        if (tid == 0) {
            float o = b_out[0];
#pragma unroll
            for (int w = 0; w < NQ; ++w) o += red[224 + w];
            out[b] = o;
        }
    }
}

extern "C" void kernel_launch(void* const* d_in, const int* in_sizes, int n_in,
                              void* d_out, int out_size)
{
    const float* x     = (const float*)d_in[0];
    const float* w_in  = (const float*)d_in[1];
    const float* b_in  = (const float*)d_in[2];
    const float* wts   = (const float*)d_in[3];
    const float* w_out = (const float*)d_in[4];
    const float* b_out = (const float*)d_in[5];
    float* out = (float*)d_out;

    const int B = in_sizes[0] / SEQL;
    const int smem = (2*DIM + 42*24 + 144 + 28 + 240) * (int)sizeof(float);

    cudaFuncSetAttribute(vqc_kernel, cudaFuncAttributeMaxDynamicSharedMemorySize, smem);
    vqc_kernel<<<B, NT, smem>>>(x, w_in, b_in, wts, w_out, b_out, out);
}